// round 2
// baseline (speedup 1.0000x reference)
#include <cuda_runtime.h>
#include <math.h>

// Model dims
#define Ln 16
#define Hn 8
#define Dn 768
#define Fn 2048
#define Vn 32000
#define DHn 96
#define Bn 2
#define Sn 1024
#define NTOK (Bn*Sn)        // 2048 tokens

typedef long long ll;

// ---------------- scratch (device globals; no allocations allowed) ----------
__device__ float g_x [NTOK*Dn];          // residual stream
__device__ float g_xn[NTOK*Dn];          // normed activations
__device__ float g_q [NTOK*Dn];
__device__ float g_k [NTOK*Dn];
__device__ float g_v [NTOK*Dn];
__device__ float g_o [NTOK*Dn];
__device__ float g_sc[Bn*Hn*Sn*Sn];      // attention scores/probs (64M floats? no: 16.7M)
__device__ float g_ff[NTOK*Fn];          // FFN hidden

// ---------------- helpers ---------------------------------------------------
__device__ __forceinline__ float gelu_tanh(float x) {
    float x3 = x * x * x;
    return 0.5f * x * (1.0f + tanhf(0.7978845608028654f * (x + 0.044715f * x3)));
}

__device__ __forceinline__ float block_reduce_sum(float v) {
    __shared__ float red[8];
    int lane = threadIdx.x & 31, wid = threadIdx.x >> 5;
    #pragma unroll
    for (int o = 16; o > 0; o >>= 1) v += __shfl_down_sync(0xffffffffu, v, o);
    __syncthreads();                       // protect red[] reuse across calls
    if (lane == 0) red[wid] = v;
    __syncthreads();
    float r = (threadIdx.x < 8) ? red[threadIdx.x] : 0.0f;
    if (wid == 0) {
        #pragma unroll
        for (int o = 4; o > 0; o >>= 1) r += __shfl_down_sync(0xffu, r, o);
        if (lane == 0) red[0] = r;
    }
    __syncthreads();
    return red[0];
}

__device__ __forceinline__ float block_reduce_max(float v) {
    __shared__ float redm[8];
    int lane = threadIdx.x & 31, wid = threadIdx.x >> 5;
    #pragma unroll
    for (int o = 16; o > 0; o >>= 1) v = fmaxf(v, __shfl_down_sync(0xffffffffu, v, o));
    __syncthreads();
    if (lane == 0) redm[wid] = v;
    __syncthreads();
    float r = (threadIdx.x < 8) ? redm[threadIdx.x] : -3.0e38f;
    if (wid == 0) {
        #pragma unroll
        for (int o = 4; o > 0; o >>= 1) r = fmaxf(r, __shfl_down_sync(0xffu, r, o));
        if (lane == 0) redm[0] = r;
    }
    __syncthreads();
    return redm[0];
}

// ---------------- fused embed + rmsnorm ------------------------------------
// x[r,:] = rmsnorm(tok_emb[tok[r]] + pos_emb[r % S], pos_norm_w)
__global__ __launch_bounds__(256)
void embed_norm_kernel(const int* __restrict__ tok,
                       const float* __restrict__ temb,
                       const float* __restrict__ pemb,
                       const float* __restrict__ w,
                       float* __restrict__ xout) {
    int r = blockIdx.x;
    int s = r & (Sn - 1);
    int t = tok[r];
    const float* te = temb + (ll)t * Dn;
    const float* pe = pemb + (ll)s * Dn;
    float v[3]; float ss = 0.0f;
    #pragma unroll
    for (int u = 0; u < 3; u++) {
        int d = threadIdx.x + u * 256;
        v[u] = te[d] + pe[d];
        ss += v[u] * v[u];
    }
    float total = block_reduce_sum(ss);
    float inv = rsqrtf(total * (1.0f / Dn) + 1e-6f);
    #pragma unroll
    for (int u = 0; u < 3; u++) {
        int d = threadIdx.x + u * 256;
        xout[(ll)r * Dn + d] = v[u] * inv * w[d];
    }
}

// ---------------- rmsnorm ---------------------------------------------------
__global__ __launch_bounds__(256)
void rmsnorm_kernel(const float* __restrict__ in, const float* __restrict__ w,
                    float* __restrict__ out) {
    int r = blockIdx.x;
    const float* xr = in + (ll)r * Dn;
    float v[3]; float ss = 0.0f;
    #pragma unroll
    for (int u = 0; u < 3; u++) {
        int d = threadIdx.x + u * 256;
        v[u] = xr[d];
        ss += v[u] * v[u];
    }
    float total = block_reduce_sum(ss);
    float inv = rsqrtf(total * (1.0f / Dn) + 1e-6f);
    #pragma unroll
    for (int u = 0; u < 3; u++) {
        int d = threadIdx.x + u * 256;
        out[(ll)r * Dn + d] = v[u] * inv * w[d];
    }
}

// ---------------- causal softmax (in-place, row length S) -------------------
__global__ __launch_bounds__(256)
void softmax_kernel(float* __restrict__ sc) {
    float* p = sc + (ll)blockIdx.x * Sn;
    float v[4]; float mx = -3.0e38f;
    #pragma unroll
    for (int u = 0; u < 4; u++) {
        v[u] = p[threadIdx.x + u * 256];
        mx = fmaxf(mx, v[u]);
    }
    float m = block_reduce_max(mx);
    float sum = 0.0f;
    #pragma unroll
    for (int u = 0; u < 4; u++) {
        v[u] = __expf(v[u] - m);       // masked entries (-1e30) -> 0
        sum += v[u];
    }
    float s = block_reduce_sum(sum);
    float invs = 1.0f / s;
    #pragma unroll
    for (int u = 0; u < 4; u++) p[threadIdx.x + u * 256] = v[u] * invs;
}

// ---------------- SGEMM: 128x128x16 tiles, 8x8/thread ----------------------
// C[M,N] = epi( alpha * A @ op(B) ), batched over z = b*Hn + h via strides.
// EPI: 0 none, 1 +Res, 2 gelu.  TB: B given as [N,K] row-major (B^T used).
// MASK: causal (col > row -> -1e30), used for QK^T scores.
#define BM 128
#define BN 128
#define BK 16

template<int EPI, bool TB, bool MASK>
__global__ __launch_bounds__(256)
void gemm_kernel(const float* __restrict__ A, int lda, ll sAb, ll sAh,
                 const float* __restrict__ Bm, int ldb, ll sBb, ll sBh,
                 const float* __restrict__ Res, ll sRb, ll sRh,
                 float* __restrict__ C, int ldc, ll sCb, ll sCh,
                 int M, int N, int K, float alpha) {
    int zb = blockIdx.z / Hn;
    int zh = blockIdx.z % Hn;
    A  += zb * sAb + zh * sAh;
    Bm += zb * sBb + zh * sBh;
    C  += zb * sCb + zh * sCh;
    if (EPI == 1) Res += zb * sRb + zh * sRh;

    __shared__ float As[BK][BM];
    __shared__ float Bs[BK][BN];

    int tid = threadIdx.x;
    int tx = tid & 15, ty = tid >> 4;
    int row0 = blockIdx.y * BM;
    int col0 = blockIdx.x * BN;

    float acc[8][8] = {};

    for (int k0 = 0; k0 < K; k0 += BK) {
        // A tile [BM][BK] -> As[k][m] (transposed). 2 float4 per thread.
        #pragma unroll
        for (int t = 0; t < 2; t++) {
            int idx = tid + t * 256;          // 0..511
            int r   = idx >> 2;               // 0..127
            int k4  = (idx & 3) * 4;          // 0,4,8,12
            float4 va = make_float4(0.f, 0.f, 0.f, 0.f);
            if (row0 + r < M)
                va = *(const float4*)(A + (ll)(row0 + r) * lda + k0 + k4);
            As[k4 + 0][r] = va.x; As[k4 + 1][r] = va.y;
            As[k4 + 2][r] = va.z; As[k4 + 3][r] = va.w;
        }
        if (!TB) {
            // B tile [BK][BN], row-major [K,N]
            #pragma unroll
            for (int t = 0; t < 2; t++) {
                int idx = tid + t * 256;
                int k   = idx >> 5;           // 0..15
                int c4  = (idx & 31) * 4;     // 0..124
                int gc  = col0 + c4;
                float4 vb = make_float4(0.f, 0.f, 0.f, 0.f);
                const float* bp = Bm + (ll)(k0 + k) * ldb + gc;
                if (gc + 3 < N) {
                    vb = *(const float4*)bp;
                } else {
                    if (gc + 0 < N) vb.x = bp[0];
                    if (gc + 1 < N) vb.y = bp[1];
                    if (gc + 2 < N) vb.z = bp[2];
                }
                *(float4*)&Bs[k][c4] = vb;
            }
        } else {
            // B is [N][K] row-major; Bs[k][c] = B[col0+c][k0+k]
            #pragma unroll
            for (int t = 0; t < 2; t++) {
                int idx = tid + t * 256;
                int c   = idx >> 2;           // 0..127
                int k4  = (idx & 3) * 4;
                int gc  = col0 + c;
                float4 vb = make_float4(0.f, 0.f, 0.f, 0.f);
                if (gc < N)
                    vb = *(const float4*)(Bm + (ll)gc * ldb + k0 + k4);
                Bs[k4 + 0][c] = vb.x; Bs[k4 + 1][c] = vb.y;
                Bs[k4 + 2][c] = vb.z; Bs[k4 + 3][c] = vb.w;
            }
        }
        __syncthreads();

        #pragma unroll
        for (int kk = 0; kk < BK; kk++) {
            float4 a0 = *(const float4*)&As[kk][ty * 8];
            float4 a1 = *(const float4*)&As[kk][ty * 8 + 4];
            float4 b0 = *(const float4*)&Bs[kk][tx * 8];
            float4 b1 = *(const float4*)&Bs[kk][tx * 8 + 4];
            float ar[8] = {a0.x, a0.y, a0.z, a0.w, a1.x, a1.y, a1.z, a1.w};
            float br[8] = {b0.x, b0.y, b0.z, b0.w, b1.x, b1.y, b1.z, b1.w};
            #pragma unroll
            for (int i = 0; i < 8; i++)
                #pragma unroll
                for (int j = 0; j < 8; j++)
                    acc[i][j] = fmaf(ar[i], br[j], acc[i][j]);
        }
        __syncthreads();
    }

    #pragma unroll
    for (int i = 0; i < 8; i++) {
        int r = row0 + ty * 8 + i;
        if (r >= M) continue;
        #pragma unroll
        for (int j = 0; j < 8; j++) {
            int c = col0 + tx * 8 + j;
            if (c >= N) continue;
            float v = acc[i][j] * alpha;
            if (MASK && c > r) v = -1e30f;
            if (EPI == 1) v += Res[(ll)r * ldc + c];
            if (EPI == 2) v = gelu_tanh(v);
            C[(ll)r * ldc + c] = v;
        }
    }
}

// ---------------- host orchestration ---------------------------------------
extern "C" void kernel_launch(void* const* d_in, const int* in_sizes, int n_in,
                              void* d_out, int out_size) {
    const int*   tok  = (const int*)  d_in[0];
    const float* temb = (const float*)d_in[1];
    const float* pemb = (const float*)d_in[2];
    const float* pnw  = (const float*)d_in[3];
    const float* anw  = (const float*)d_in[4];
    const float* wq   = (const float*)d_in[5];
    const float* wk   = (const float*)d_in[6];
    const float* wv   = (const float*)d_in[7];
    const float* wo   = (const float*)d_in[8];
    const float* fnw  = (const float*)d_in[9];
    const float* w1   = (const float*)d_in[10];
    const float* w2   = (const float*)d_in[11];
    const float* onw  = (const float*)d_in[12];
    const float* oww  = (const float*)d_in[13];
    float* out = (float*)d_out;

    float *x, *xn, *q, *k, *v, *o, *sc, *ff;
    cudaGetSymbolAddress((void**)&x,  g_x);
    cudaGetSymbolAddress((void**)&xn, g_xn);
    cudaGetSymbolAddress((void**)&q,  g_q);
    cudaGetSymbolAddress((void**)&k,  g_k);
    cudaGetSymbolAddress((void**)&v,  g_v);
    cudaGetSymbolAddress((void**)&o,  g_o);
    cudaGetSymbolAddress((void**)&sc, g_sc);
    cudaGetSymbolAddress((void**)&ff, g_ff);

    const float scale = 1.0f / sqrtf((float)DHn);

    embed_norm_kernel<<<NTOK, 256>>>(tok, temb, pemb, pnw, x);

    dim3 gD(Dn / BN, NTOK / BM);              // (6,16)  2048 x 768
    dim3 gF(Fn / BN, NTOK / BM);              // (16,16) 2048 x 2048
    dim3 gSc(Sn / BN, Sn / BM, Bn * Hn);      // (8,8,16) scores per (b,h)
    dim3 gPV(1, Sn / BM, Bn * Hn);            // (1,8,16) probs @ V, N=96
    dim3 gV(Vn / BN, NTOK / BM);              // (250,16) logits

    const ll sQb = (ll)Sn * Dn, sQh = DHn;                    // q/k/v/o per-(b,h)
    const ll sScb = (ll)Hn * Sn * Sn, sSch = (ll)Sn * Sn;     // scores per-(b,h)

    for (int l = 0; l < Ln; l++) {
        rmsnorm_kernel<<<NTOK, 256>>>(x, anw + (ll)l * Dn, xn);

        gemm_kernel<0, false, false><<<gD, 256>>>(
            xn, Dn, 0, 0, wq + (ll)l * Dn * Dn, Dn, 0, 0,
            nullptr, 0, 0, q, Dn, 0, 0, NTOK, Dn, Dn, 1.0f);
        gemm_kernel<0, false, false><<<gD, 256>>>(
            xn, Dn, 0, 0, wk + (ll)l * Dn * Dn, Dn, 0, 0,
            nullptr, 0, 0, k, Dn, 0, 0, NTOK, Dn, Dn, 1.0f);
        gemm_kernel<0, false, false><<<gD, 256>>>(
            xn, Dn, 0, 0, wv + (ll)l * Dn * Dn, Dn, 0, 0,
            nullptr, 0, 0, v, Dn, 0, 0, NTOK, Dn, Dn, 1.0f);

        // scores = scale * Q @ K^T, causal mask
        gemm_kernel<0, true, true><<<gSc, 256>>>(
            q, Dn, sQb, sQh, k, Dn, sQb, sQh,
            nullptr, 0, 0, sc, Sn, sScb, sSch, Sn, Sn, DHn, scale);

        softmax_kernel<<<Bn * Hn * Sn, 256>>>(sc);

        // o = probs @ V
        gemm_kernel<0, false, false><<<gPV, 256>>>(
            sc, Sn, sScb, sSch, v, Dn, sQb, sQh,
            nullptr, 0, 0, o, Dn, sQb, sQh, Sn, DHn, Sn, 1.0f);

        // x = x + o @ Wo
        gemm_kernel<1, false, false><<<gD, 256>>>(
            o, Dn, 0, 0, wo + (ll)l * Dn * Dn, Dn, 0, 0,
            x, 0, 0, x, Dn, 0, 0, NTOK, Dn, Dn, 1.0f);

        rmsnorm_kernel<<<NTOK, 256>>>(x, fnw + (ll)l * Dn, xn);

        // ff = gelu(xn @ W1)
        gemm_kernel<2, false, false><<<gF, 256>>>(
            xn, Dn, 0, 0, w1 + (ll)l * Dn * Fn, Fn, 0, 0,
            nullptr, 0, 0, ff, Fn, 0, 0, NTOK, Fn, Dn, 1.0f);

        // x = x + ff @ W2
        gemm_kernel<1, false, false><<<gD, 256>>>(
            ff, Fn, 0, 0, w2 + (ll)l * Fn * Dn, Dn, 0, 0,
            x, 0, 0, x, Dn, 0, 0, NTOK, Dn, Fn, 1.0f);
    }

    rmsnorm_kernel<<<NTOK, 256>>>(x, onw, xn);

    // logits = xn @ out_w
    gemm_kernel<0, false, false><<<gV, 256>>>(
        xn, Dn, 0, 0, oww, Vn, 0, 0,
        nullptr, 0, 0, out, Vn, 0, 0, NTOK, Vn, Dn, 1.0f);
}

// round 5
// speedup vs baseline: 2.3873x; 2.3873x over previous
#include <cuda_runtime.h>
#include <cuda_bf16.h>
#include <mma.h>
#include <math.h>
#include <stdint.h>

#define Ln 16
#define Hn 8
#define Dn 768
#define Fn 2048
#define Vn 32000
#define DHn 96
#define Bn 2
#define Sn 1024
#define NTOK (Bn*Sn)

typedef long long ll;
typedef __nv_bfloat16 bf16;
using namespace nvcuda;

// ---------------- scratch (device globals) ----------------------------------
__device__ float g_x [NTOK*Dn];
__device__ float g_sc[Bn*Hn*Sn*Sn];
__device__ bf16  g_xn_hi [NTOK*Dn],   g_xn_mid [NTOK*Dn];
__device__ bf16  g_qkv_hi[NTOK*3*Dn], g_qkv_mid[NTOK*3*Dn];
__device__ bf16  g_vt_hi [Dn*NTOK],   g_vt_mid [Dn*NTOK];
__device__ bf16  g_o_hi  [NTOK*Dn],   g_o_mid  [NTOK*Dn];
__device__ bf16  g_p_hi  [Bn*Hn*Sn*Sn], g_p_mid[Bn*Hn*Sn*Sn];
__device__ bf16  g_h_hi  [NTOK*Fn],   g_h_mid  [NTOK*Fn];
__device__ bf16  g_wqkvT_hi[Ln*3*Dn*Dn], g_wqkvT_mid[Ln*3*Dn*Dn];
__device__ bf16  g_woT_hi[Ln*Dn*Dn],  g_woT_mid[Ln*Dn*Dn];
__device__ bf16  g_w1T_hi[(ll)Ln*Dn*Fn], g_w1T_mid[(ll)Ln*Dn*Fn];
__device__ bf16  g_w2T_hi[(ll)Ln*Dn*Fn], g_w2T_mid[(ll)Ln*Dn*Fn];
__device__ bf16  g_owT_hi[(ll)Vn*Dn], g_owT_mid[(ll)Vn*Dn];

// ---------------- helpers ----------------------------------------------------
__device__ __forceinline__ uint32_t smem_u32(const void* p) {
    uint32_t a;
    asm("{ .reg .u64 t; cvta.to.shared.u64 t, %1; cvt.u32.u64 %0, t; }" : "=r"(a) : "l"(p));
    return a;
}
__device__ __forceinline__ void cpa16(uint32_t dst, const void* src, int ok) {
    int sz = ok ? 16 : 0;
    asm volatile("cp.async.cg.shared.global [%0], [%1], 16, %2;\n"
                 :: "r"(dst), "l"(src), "r"(sz));
}
#define CP_COMMIT() asm volatile("cp.async.commit_group;" ::: "memory")

__device__ __forceinline__ float gelu_tanh(float x) {
    float x3 = x * x * x;
    return 0.5f * x * (1.0f + tanhf(0.7978845608028654f * (x + 0.044715f * x3)));
}
__device__ __forceinline__ void split2(float v, bf16& h, bf16& m) {
    h = __float2bfloat16(v);
    m = __float2bfloat16(v - __bfloat162float(h));
}

__device__ __forceinline__ float block_sum(float v) {
    __shared__ float red[8];
    int lane = threadIdx.x & 31, wid = threadIdx.x >> 5;
    #pragma unroll
    for (int o = 16; o > 0; o >>= 1) v += __shfl_down_sync(0xffffffffu, v, o);
    __syncthreads();
    if (lane == 0) red[wid] = v;
    __syncthreads();
    float r = (threadIdx.x < 8) ? red[threadIdx.x] : 0.0f;
    if (wid == 0) {
        #pragma unroll
        for (int o = 4; o > 0; o >>= 1) r += __shfl_down_sync(0xffu, r, o);
        if (lane == 0) red[0] = r;
    }
    __syncthreads();
    return red[0];
}
__device__ __forceinline__ float block_max(float v) {
    __shared__ float redm[8];
    int lane = threadIdx.x & 31, wid = threadIdx.x >> 5;
    #pragma unroll
    for (int o = 16; o > 0; o >>= 1) v = fmaxf(v, __shfl_down_sync(0xffffffffu, v, o));
    __syncthreads();
    if (lane == 0) redm[wid] = v;
    __syncthreads();
    float r = (threadIdx.x < 8) ? redm[threadIdx.x] : -3.0e38f;
    if (wid == 0) {
        #pragma unroll
        for (int o = 4; o > 0; o >>= 1) r = fmaxf(r, __shfl_down_sync(0xffu, r, o));
        if (lane == 0) redm[0] = r;
    }
    __syncthreads();
    return redm[0];
}

// ---------------- small kernels ----------------------------------------------
__global__ __launch_bounds__(256)
void embed_norm_kernel(const int* __restrict__ tok, const float* __restrict__ temb,
                       const float* __restrict__ pemb, const float* __restrict__ w,
                       float* __restrict__ xout) {
    int r = blockIdx.x, s = r & (Sn - 1), t = tok[r];
    const float* te = temb + (ll)t * Dn;
    const float* pe = pemb + (ll)s * Dn;
    float v[3]; float ss = 0.0f;
    #pragma unroll
    for (int u = 0; u < 3; u++) {
        int d = threadIdx.x + u * 256;
        v[u] = te[d] + pe[d];
        ss += v[u] * v[u];
    }
    float inv = rsqrtf(block_sum(ss) * (1.0f / Dn) + 1e-6f);
    #pragma unroll
    for (int u = 0; u < 3; u++) {
        int d = threadIdx.x + u * 256;
        xout[(ll)r * Dn + d] = v[u] * inv * w[d];
    }
}

__global__ __launch_bounds__(256)
void rmsnorm_split_kernel(const float* __restrict__ in, const float* __restrict__ w,
                          bf16* __restrict__ oh, bf16* __restrict__ om) {
    int r = blockIdx.x;
    const float* xr = in + (ll)r * Dn;
    float v[3]; float ss = 0.0f;
    #pragma unroll
    for (int u = 0; u < 3; u++) {
        int d = threadIdx.x + u * 256;
        v[u] = xr[d];
        ss += v[u] * v[u];
    }
    float inv = rsqrtf(block_sum(ss) * (1.0f / Dn) + 1e-6f);
    #pragma unroll
    for (int u = 0; u < 3; u++) {
        int d = threadIdx.x + u * 256;
        bf16 h, m;
        split2(v[u] * inv * w[d], h, m);
        oh[(ll)r * Dn + d] = h;
        om[(ll)r * Dn + d] = m;
    }
}

__global__ __launch_bounds__(256)
void softmax_split_kernel(const float* __restrict__ sc,
                          bf16* __restrict__ ph, bf16* __restrict__ pm) {
    ll base = (ll)blockIdx.x * Sn;
    const float* p = sc + base;
    float v[4]; float mx = -3.0e38f;
    #pragma unroll
    for (int u = 0; u < 4; u++) {
        v[u] = p[threadIdx.x + u * 256];
        mx = fmaxf(mx, v[u]);
    }
    float m = block_max(mx);
    float sum = 0.0f;
    #pragma unroll
    for (int u = 0; u < 4; u++) { v[u] = __expf(v[u] - m); sum += v[u]; }
    float invs = 1.0f / block_sum(sum);
    #pragma unroll
    for (int u = 0; u < 4; u++) {
        bf16 h, mm;
        split2(v[u] * invs, h, mm);
        ph[base + threadIdx.x + u * 256] = h;
        pm[base + threadIdx.x + u * 256] = mm;
    }
}

// transpose + split: out[n][k] = W[k][n], fp32 -> bf16 hi/mid.  grid(N/32,K/32,L)
__global__ __launch_bounds__(256)
void wtrans_kernel(const float* __restrict__ W, bf16* __restrict__ Th,
                   bf16* __restrict__ Tm, int K, int N,
                   ll inLS, ll outLS, int outRowOff, int outLd) {
    __shared__ float t[32][33];
    int l = blockIdx.z;
    W  += (ll)l * inLS;
    Th += (ll)l * outLS;
    Tm += (ll)l * outLS;
    int n0 = blockIdx.x * 32, k0 = blockIdx.y * 32;
    int tx = threadIdx.x & 31, ty = threadIdx.x >> 5;
    #pragma unroll
    for (int j = 0; j < 32; j += 8)
        t[ty + j][tx] = W[(ll)(k0 + ty + j) * N + n0 + tx];
    __syncthreads();
    #pragma unroll
    for (int j = 0; j < 32; j += 8) {
        float v = t[tx][ty + j];
        bf16 h, m;
        split2(v, h, m);
        ll idx = (ll)(outRowOff + n0 + ty + j) * outLd + k0 + tx;
        Th[idx] = h;
        Tm[idx] = m;
    }
}

// bf16 pair transpose of V part of qkv: vt[d][t] = qkv[t][1536+d]
__global__ __launch_bounds__(256)
void vtrans_kernel(const bf16* __restrict__ ih, const bf16* __restrict__ im,
                   bf16* __restrict__ oh, bf16* __restrict__ om) {
    __shared__ bf16 th[32][33], tm[32][33];
    int d0 = blockIdx.x * 32, t0 = blockIdx.y * 32;
    int tx = threadIdx.x & 31, ty = threadIdx.x >> 5;
    #pragma unroll
    for (int j = 0; j < 32; j += 8) {
        ll idx = (ll)(t0 + ty + j) * (3 * Dn) + 1536 + d0 + tx;
        th[ty + j][tx] = ih[idx];
        tm[ty + j][tx] = im[idx];
    }
    __syncthreads();
    #pragma unroll
    for (int j = 0; j < 32; j += 8) {
        ll idx = (ll)(d0 + ty + j) * NTOK + t0 + tx;
        oh[idx] = th[tx][ty + j];
        om[idx] = tm[tx][ty + j];
    }
}

// ---------------- WMMA bf16-split GEMM ---------------------------------------
// C[128,128 tile] = epi( alpha * A @ B^T ), A[M,K] bf16 hi/mid row-major,
// B[N,K] bf16 hi/mid row-major.  3 products: AhBh + AmBh + AhBm (fp32 acc).
// EPI: 0 fp32 (+opt causal MASK) | 1 fp32 + Res | 2 bf16 split | 3 gelu split
#define SA 40                      // smem row stride in bf16 elements (80B)
#define TILEB (128 * SA * 2)       // one operand tile: 10240 bytes
#define STG (4 * TILEB)            // stage: Ah Am Bh Bm = 40960 bytes
#define SMEMSZ (2 * STG)           // 81920 (epilogue staging aliases this)

template<int EPI, bool MASK>
__global__ __launch_bounds__(256, 1)
void mm_kernel(const bf16* __restrict__ Ahi, const bf16* __restrict__ Amid,
               int lda, ll sAb, ll sAh,
               const bf16* __restrict__ Bhi, const bf16* __restrict__ Bmid,
               int ldb, ll sBb, ll sBh,
               const float* __restrict__ Res,
               float* __restrict__ Cf, bf16* __restrict__ Chi, bf16* __restrict__ Cmid,
               int ldc, ll sCb, ll sCh,
               int N, int K, float alpha, int zdiv) {
    extern __shared__ char smem[];
    uint32_t sb = smem_u32(smem);
    int tid = threadIdx.x, wid = tid >> 5;
    int wr = wid >> 2, wc = wid & 3;           // warp tile: rows [wr*64), cols [wc*32)

    int zb = blockIdx.z / zdiv, zh = blockIdx.z % zdiv;
    Ahi += zb * sAb + zh * sAh;  Amid += zb * sAb + zh * sAh;
    Bhi += zb * sBb + zh * sBh;  Bmid += zb * sBb + zh * sBh;
    ll co = zb * sCb + zh * sCh;
    int row0 = blockIdx.y * 128, col0 = blockIdx.x * 128;

    auto issue_loads = [&](int ci) {
        uint32_t st = sb + (ci & 1) * STG;
        int k0 = ci * 32;
        #pragma unroll
        for (int t = 0; t < 2; t++) {
            int idx = tid + t * 256;           // 0..511
            int r  = idx >> 2;                 // 0..127
            int cb = (idx & 3) * 16;           // byte col in row (0..48)
            int ke = cb >> 1;                  // element col
            ll ga = (ll)(row0 + r) * lda + k0 + ke;
            cpa16(st + r * 80 + cb,              Ahi  + ga, 1);
            cpa16(st + TILEB + r * 80 + cb,      Amid + ga, 1);
            int ok = (col0 + r) < N;
            ll gb = ok ? ((ll)(col0 + r) * ldb + k0 + ke) : 0;
            cpa16(st + 2 * TILEB + r * 80 + cb,  Bhi  + gb, ok);
            cpa16(st + 3 * TILEB + r * 80 + cb,  Bmid + gb, ok);
        }
        CP_COMMIT();
    };

    wmma::fragment<wmma::accumulator, 16, 16, 16, float> acc[4][2];
    #pragma unroll
    for (int mi = 0; mi < 4; mi++)
        #pragma unroll
        for (int ni = 0; ni < 2; ni++)
            wmma::fill_fragment(acc[mi][ni], 0.0f);

    int nk = K >> 5;
    issue_loads(0);
    if (nk > 1) issue_loads(1);

    for (int i = 0; i < nk; i++) {
        if (i + 1 < nk) asm volatile("cp.async.wait_group 1;" ::: "memory");
        else            asm volatile("cp.async.wait_group 0;" ::: "memory");
        __syncthreads();

        const bf16* base = (const bf16*)(smem + (i & 1) * STG);
        const bf16* sAh_ = base;
        const bf16* sAm_ = base + 128 * SA;
        const bf16* sBh_ = base + 2 * 128 * SA;
        const bf16* sBm_ = base + 3 * 128 * SA;

        #pragma unroll
        for (int kk = 0; kk < 32; kk += 16) {
            wmma::fragment<wmma::matrix_a, 16, 16, 16, bf16, wmma::row_major> ah[4], am[4];
            wmma::fragment<wmma::matrix_b, 16, 16, 16, bf16, wmma::col_major> bh[2], bm[2];
            #pragma unroll
            for (int mi = 0; mi < 4; mi++) {
                int rr = wr * 64 + mi * 16;
                wmma::load_matrix_sync(ah[mi], sAh_ + rr * SA + kk, SA);
                wmma::load_matrix_sync(am[mi], sAm_ + rr * SA + kk, SA);
            }
            #pragma unroll
            for (int ni = 0; ni < 2; ni++) {
                int cc = wc * 32 + ni * 16;
                wmma::load_matrix_sync(bh[ni], sBh_ + cc * SA + kk, SA);
                wmma::load_matrix_sync(bm[ni], sBm_ + cc * SA + kk, SA);
            }
            #pragma unroll
            for (int mi = 0; mi < 4; mi++)
                #pragma unroll
                for (int ni = 0; ni < 2; ni++) {
                    wmma::mma_sync(acc[mi][ni], ah[mi], bh[ni], acc[mi][ni]);
                    wmma::mma_sync(acc[mi][ni], am[mi], bh[ni], acc[mi][ni]);
                    wmma::mma_sync(acc[mi][ni], ah[mi], bm[ni], acc[mi][ni]);
                }
        }
        __syncthreads();                        // stage reads done before refill
        if (i + 2 < nk) issue_loads(i + 2);
    }

    // ---- epilogue: stage accumulators in smem (aliases pipeline buffers) ----
    float* Cs = (float*)smem;                   // [128][132]
    #pragma unroll
    for (int mi = 0; mi < 4; mi++)
        #pragma unroll
        for (int ni = 0; ni < 2; ni++)
            wmma::store_matrix_sync(Cs + (wr * 64 + mi * 16) * 132 + wc * 32 + ni * 16,
                                    acc[mi][ni], 132, wmma::mem_row_major);
    __syncthreads();

    int er = tid >> 1;                          // 0..127
    int c0 = (tid & 1) * 64;
    int gr = row0 + er;
    const float* crow = Cs + er * 132 + c0;

    if (EPI <= 1) {
        #pragma unroll
        for (int j = 0; j < 64; j += 4) {
            int c = col0 + c0 + j;
            float4 v;
            v.x = crow[j + 0] * alpha;
            v.y = crow[j + 1] * alpha;
            v.z = crow[j + 2] * alpha;
            v.w = crow[j + 3] * alpha;
            if (MASK) {
                if (c + 0 > gr) v.x = -1e30f;
                if (c + 1 > gr) v.y = -1e30f;
                if (c + 2 > gr) v.z = -1e30f;
                if (c + 3 > gr) v.w = -1e30f;
            }
            if (EPI == 1) {
                const float4 rs = *(const float4*)(Res + (ll)gr * ldc + c);
                v.x += rs.x; v.y += rs.y; v.z += rs.z; v.w += rs.w;
            }
            *(float4*)(Cf + co + (ll)gr * ldc + c) = v;
        }
    } else {
        #pragma unroll
        for (int j = 0; j < 64; j += 2) {
            int c = col0 + c0 + j;
            if (c >= N) continue;
            float v0 = crow[j + 0] * alpha;
            float v1 = crow[j + 1] * alpha;
            if (EPI == 3) { v0 = gelu_tanh(v0); v1 = gelu_tanh(v1); }
            bf16 h0, m0, h1, m1;
            split2(v0, h0, m0);
            split2(v1, h1, m1);
            ll idx = co + (ll)gr * ldc + c;
            *(__nv_bfloat162*)(Chi + idx)  = __nv_bfloat162(h0, h1);
            *(__nv_bfloat162*)(Cmid + idx) = __nv_bfloat162(m0, m1);
        }
    }
}

// ---------------- host orchestration -----------------------------------------
extern "C" void kernel_launch(void* const* d_in, const int* in_sizes, int n_in,
                              void* d_out, int out_size) {
    const int*   tok  = (const int*)  d_in[0];
    const float* temb = (const float*)d_in[1];
    const float* pemb = (const float*)d_in[2];
    const float* pnw  = (const float*)d_in[3];
    const float* anw  = (const float*)d_in[4];
    const float* wq   = (const float*)d_in[5];
    const float* wk   = (const float*)d_in[6];
    const float* wv   = (const float*)d_in[7];
    const float* wo   = (const float*)d_in[8];
    const float* fnw  = (const float*)d_in[9];
    const float* w1   = (const float*)d_in[10];
    const float* w2   = (const float*)d_in[11];
    const float* onw  = (const float*)d_in[12];
    const float* oww  = (const float*)d_in[13];
    float* out = (float*)d_out;

    float *x, *sc;
    bf16 *xnh, *xnm, *qkh, *qkm, *vth, *vtm, *oh, *om, *ph, *pm, *hh, *hm;
    bf16 *wqkh, *wqkm, *woh, *wom, *w1h, *w1m, *w2h, *w2m, *owh, *owm;
    cudaGetSymbolAddress((void**)&x,   g_x);
    cudaGetSymbolAddress((void**)&sc,  g_sc);
    cudaGetSymbolAddress((void**)&xnh, g_xn_hi);   cudaGetSymbolAddress((void**)&xnm, g_xn_mid);
    cudaGetSymbolAddress((void**)&qkh, g_qkv_hi);  cudaGetSymbolAddress((void**)&qkm, g_qkv_mid);
    cudaGetSymbolAddress((void**)&vth, g_vt_hi);   cudaGetSymbolAddress((void**)&vtm, g_vt_mid);
    cudaGetSymbolAddress((void**)&oh,  g_o_hi);    cudaGetSymbolAddress((void**)&om,  g_o_mid);
    cudaGetSymbolAddress((void**)&ph,  g_p_hi);    cudaGetSymbolAddress((void**)&pm,  g_p_mid);
    cudaGetSymbolAddress((void**)&hh,  g_h_hi);    cudaGetSymbolAddress((void**)&hm,  g_h_mid);
    cudaGetSymbolAddress((void**)&wqkh,g_wqkvT_hi);cudaGetSymbolAddress((void**)&wqkm,g_wqkvT_mid);
    cudaGetSymbolAddress((void**)&woh, g_woT_hi);  cudaGetSymbolAddress((void**)&wom, g_woT_mid);
    cudaGetSymbolAddress((void**)&w1h, g_w1T_hi);  cudaGetSymbolAddress((void**)&w1m, g_w1T_mid);
    cudaGetSymbolAddress((void**)&w2h, g_w2T_hi);  cudaGetSymbolAddress((void**)&w2m, g_w2T_mid);
    cudaGetSymbolAddress((void**)&owh, g_owT_hi);  cudaGetSymbolAddress((void**)&owm, g_owT_mid);

    cudaFuncSetAttribute(mm_kernel<2, false>, cudaFuncAttributeMaxDynamicSharedMemorySize, SMEMSZ);
    cudaFuncSetAttribute(mm_kernel<0, true >, cudaFuncAttributeMaxDynamicSharedMemorySize, SMEMSZ);
    cudaFuncSetAttribute(mm_kernel<3, false>, cudaFuncAttributeMaxDynamicSharedMemorySize, SMEMSZ);
    cudaFuncSetAttribute(mm_kernel<0, false>, cudaFuncAttributeMaxDynamicSharedMemorySize, SMEMSZ);
    cudaFuncSetAttribute(mm_kernel<1, false>, cudaFuncAttributeMaxDynamicSharedMemorySize, SMEMSZ);

    const float scale = 1.0f / sqrtf((float)DHn);

    // ---- weight transposes + splits ----
    wtrans_kernel<<<dim3(24, 24, Ln), 256>>>(wq, wqkh, wqkm, Dn, Dn,
        (ll)Dn * Dn, (ll)3 * Dn * Dn, 0, Dn);
    wtrans_kernel<<<dim3(24, 24, Ln), 256>>>(wk, wqkh, wqkm, Dn, Dn,
        (ll)Dn * Dn, (ll)3 * Dn * Dn, Dn, Dn);
    wtrans_kernel<<<dim3(24, 24, Ln), 256>>>(wv, wqkh, wqkm, Dn, Dn,
        (ll)Dn * Dn, (ll)3 * Dn * Dn, 2 * Dn, Dn);
    wtrans_kernel<<<dim3(24, 24, Ln), 256>>>(wo, woh, wom, Dn, Dn,
        (ll)Dn * Dn, (ll)Dn * Dn, 0, Dn);
    wtrans_kernel<<<dim3(64, 24, Ln), 256>>>(w1, w1h, w1m, Dn, Fn,
        (ll)Dn * Fn, (ll)Dn * Fn, 0, Dn);
    wtrans_kernel<<<dim3(24, 64, Ln), 256>>>(w2, w2h, w2m, Fn, Dn,
        (ll)Fn * Dn, (ll)Fn * Dn, 0, Fn);
    wtrans_kernel<<<dim3(1000, 24, 1), 256>>>(oww, owh, owm, Dn, Vn,
        (ll)Dn * Vn, (ll)Dn * Vn, 0, Dn);

    embed_norm_kernel<<<NTOK, 256>>>(tok, temb, pemb, pnw, x);

    const ll sAb_qk = (ll)Sn * 3 * Dn;
    const ll sScb = (ll)Hn * Sn * Sn, sSch = (ll)Sn * Sn;

    for (int l = 0; l < Ln; l++) {
        rmsnorm_split_kernel<<<NTOK, 256>>>(x, anw + (ll)l * Dn, xnh, xnm);

        // qkv = xn @ WqkvT^T   [2048 x 2304]
        mm_kernel<2, false><<<dim3(18, 16, 1), 256, SMEMSZ>>>(
            xnh, xnm, Dn, 0, 0,
            wqkh + (ll)l * 3 * Dn * Dn, wqkm + (ll)l * 3 * Dn * Dn, Dn, 0, 0,
            nullptr, nullptr, qkh, qkm, 3 * Dn, 0, 0,
            3 * Dn, Dn, 1.0f, 1);

        vtrans_kernel<<<dim3(24, 64), 256>>>(qkh, qkm, vth, vtm);

        // scores = scale * Q @ K^T + causal mask
        mm_kernel<0, true><<<dim3(8, 8, Bn * Hn), 256, SMEMSZ>>>(
            qkh, qkm, 3 * Dn, sAb_qk, DHn,
            qkh + Dn, qkm + Dn, 3 * Dn, sAb_qk, DHn,
            nullptr, sc, nullptr, nullptr, Sn, sScb, sSch,
            Sn, DHn, scale, Hn);

        softmax_split_kernel<<<Bn * Hn * Sn, 256>>>(sc, ph, pm);

        // o = probs @ V
        mm_kernel<2, false><<<dim3(1, 8, Bn * Hn), 256, SMEMSZ>>>(
            ph, pm, Sn, sScb, sSch,
            vth, vtm, NTOK, (ll)Sn, (ll)DHn * NTOK,
            nullptr, nullptr, oh, om, Dn, (ll)Sn * Dn, (ll)DHn,
            DHn, Sn, 1.0f, Hn);

        // x = x + o @ WoT^T
        mm_kernel<1, false><<<dim3(6, 16, 1), 256, SMEMSZ>>>(
            oh, om, Dn, 0, 0,
            woh + (ll)l * Dn * Dn, wom + (ll)l * Dn * Dn, Dn, 0, 0,
            x, x, nullptr, nullptr, Dn, 0, 0,
            Dn, Dn, 1.0f, 1);

        rmsnorm_split_kernel<<<NTOK, 256>>>(x, fnw + (ll)l * Dn, xnh, xnm);

        // h = gelu(xn @ W1T^T)
        mm_kernel<3, false><<<dim3(16, 16, 1), 256, SMEMSZ>>>(
            xnh, xnm, Dn, 0, 0,
            w1h + (ll)l * Dn * Fn, w1m + (ll)l * Dn * Fn, Dn, 0, 0,
            nullptr, nullptr, hh, hm, Fn, 0, 0,
            Fn, Dn, 1.0f, 1);

        // x = x + h @ W2T^T
        mm_kernel<1, false><<<dim3(6, 16, 1), 256, SMEMSZ>>>(
            hh, hm, Fn, 0, 0,
            w2h + (ll)l * Dn * Fn, w2m + (ll)l * Dn * Fn, Fn, 0, 0,
            x, x, nullptr, nullptr, Dn, 0, 0,
            Dn, Fn, 1.0f, 1);
    }

    rmsnorm_split_kernel<<<NTOK, 256>>>(x, onw, xnh, xnm);

    // logits = xn @ OwT^T
    mm_kernel<0, false><<<dim3(250, 16, 1), 256, SMEMSZ>>>(
        xnh, xnm, Dn, 0, 0,
        owh, owm, Dn, 0, 0,
        nullptr, out, nullptr, nullptr, Vn, 0, 0,
        Vn, Dn, 1.0f, 1);
}